// round 1
// baseline (speedup 1.0000x reference)
#include <cuda_runtime.h>
#include <math.h>
#include <stdint.h>

// ---------------- problem dims ----------------
#define BATCH   4
#define S_IN    1028
#define D_IN    64
#define S1      1026      // after conv1 (VALID, k=3)
#define SEQ     1024      // after conv2
#define DH      512       // D/2
#define D_MODEL 1024
#define NHEAD   16
#define HDIM    64
#define NLAYER  4
#define FFDIM   2048
#define EPSF    1e-6f

// ---------------- scratch (device globals; no allocation allowed) ----------------
__device__ float g_h  [BATCH*SEQ*D_MODEL];
__device__ float g_hn [BATCH*SEQ*D_MODEL];
__device__ float g_q  [BATCH*SEQ*D_MODEL];
__device__ float g_k  [BATCH*SEQ*D_MODEL];
__device__ float g_v  [BATCH*SEQ*D_MODEL];
__device__ float g_wv [BATCH*SEQ*D_MODEL];
__device__ float g_ff [BATCH*SEQ*FFDIM];
__device__ float g_h1 [BATCH*S1*DH];
__device__ float g_im1[(size_t)BATCH*S1*192];
__device__ float g_im2[(size_t)BATCH*SEQ*1536];
__device__ float g_w1r[DH*192];
__device__ float g_w2r[D_MODEL*1536];
__device__ float g_pool[BATCH*D_MODEL];

// ---------------- generic SGEMM: C[M,N] = A[M,K] @ B[N,K]^T + bias (+relu) (+resid) ----------------
#define BM 128
#define BN 128
#define BK 16

template<bool RELU, bool RESID>
__global__ void __launch_bounds__(256, 2) sgemm_tn(
    const float* __restrict__ A, const float* __restrict__ B,
    const float* __restrict__ bias, const float* __restrict__ resid,
    float* __restrict__ C, int M, int N, int K)
{
    __shared__ float As[BK][BM];
    __shared__ float Bs[BK][BN];

    const int tid  = threadIdx.x;
    const int crow = blockIdx.y * BM;
    const int ccol = blockIdx.x * BN;
    const int lrow = tid >> 2;            // 0..63
    const int lcol = (tid & 3) << 2;      // 0,4,8,12
    const int ty   = tid >> 4;            // 0..15
    const int tx   = tid & 15;            // 0..15

    float acc[8][8];
#pragma unroll
    for (int i = 0; i < 8; i++)
#pragma unroll
        for (int j = 0; j < 8; j++) acc[i][j] = 0.f;

    for (int k0 = 0; k0 < K; k0 += BK) {
#pragma unroll
        for (int half = 0; half < 2; half++) {
            int r  = lrow + half * 64;
            int gr = crow + r; if (gr > M - 1) gr = M - 1;     // clamp (stores guarded)
            float4 a4 = *reinterpret_cast<const float4*>(&A[(size_t)gr * K + k0 + lcol]);
            As[lcol + 0][r] = a4.x; As[lcol + 1][r] = a4.y;
            As[lcol + 2][r] = a4.z; As[lcol + 3][r] = a4.w;
            int gn = ccol + r;                                  // N always multiple of BN here
            float4 b4 = *reinterpret_cast<const float4*>(&B[(size_t)gn * K + k0 + lcol]);
            Bs[lcol + 0][r] = b4.x; Bs[lcol + 1][r] = b4.y;
            Bs[lcol + 2][r] = b4.z; Bs[lcol + 3][r] = b4.w;
        }
        __syncthreads();
#pragma unroll
        for (int k = 0; k < BK; k++) {
            float4 a0 = *reinterpret_cast<const float4*>(&As[k][ty * 8]);
            float4 a1 = *reinterpret_cast<const float4*>(&As[k][ty * 8 + 4]);
            float4 b0 = *reinterpret_cast<const float4*>(&Bs[k][tx * 8]);
            float4 b1 = *reinterpret_cast<const float4*>(&Bs[k][tx * 8 + 4]);
            float ra[8] = {a0.x, a0.y, a0.z, a0.w, a1.x, a1.y, a1.z, a1.w};
            float rb[8] = {b0.x, b0.y, b0.z, b0.w, b1.x, b1.y, b1.z, b1.w};
#pragma unroll
            for (int i = 0; i < 8; i++)
#pragma unroll
                for (int j = 0; j < 8; j++)
                    acc[i][j] = fmaf(ra[i], rb[j], acc[i][j]);
        }
        __syncthreads();
    }

#pragma unroll
    for (int i = 0; i < 8; i++) {
        int gr = crow + ty * 8 + i;
        if (gr >= M) continue;
        size_t rowoff = (size_t)gr * N;
#pragma unroll
        for (int j = 0; j < 8; j += 4) {
            int gn = ccol + tx * 8 + j;
            float4 v = make_float4(acc[i][j], acc[i][j + 1], acc[i][j + 2], acc[i][j + 3]);
            if (bias) {
                v.x += bias[gn]; v.y += bias[gn + 1]; v.z += bias[gn + 2]; v.w += bias[gn + 3];
            }
            if (RELU) {
                v.x = fmaxf(v.x, 0.f); v.y = fmaxf(v.y, 0.f);
                v.z = fmaxf(v.z, 0.f); v.w = fmaxf(v.w, 0.f);
            }
            if (RESID) {
                float4 r4 = *reinterpret_cast<const float4*>(&resid[rowoff + gn]);
                v.x += r4.x; v.y += r4.y; v.z += r4.z; v.w += r4.w;
            }
            *reinterpret_cast<float4*>(&C[rowoff + gn]) = v;
        }
    }
}

// ---------------- im2col + weight repack for the conv frontend ----------------
__global__ void im2col1_kernel(const float* __restrict__ x, float* __restrict__ out)
{
    const int COLS4 = 192 / 4;
    int idx = blockIdx.x * 256 + threadIdx.x;
    if (idx >= BATCH * S1 * COLS4) return;
    int m  = idx / COLS4;
    int c4 = (idx % COLS4) * 4;
    int b  = m / S1, s = m % S1;
    int kk = c4 / D_IN, ic = c4 % D_IN;
    float4 v = *reinterpret_cast<const float4*>(&x[((size_t)(b * S_IN + s + kk)) * D_IN + ic]);
    *reinterpret_cast<float4*>(&out[(size_t)m * 192 + c4]) = v;
}

__global__ void im2col2_kernel(const float* __restrict__ h1, float* __restrict__ out)
{
    const int COLS4 = 1536 / 4;
    int idx = blockIdx.x * 256 + threadIdx.x;
    if (idx >= BATCH * SEQ * COLS4) return;
    int m  = idx / COLS4;
    int c4 = (idx % COLS4) * 4;
    int b  = m / SEQ, s = m % SEQ;
    int kk = c4 / DH, ic = c4 % DH;
    float4 v = *reinterpret_cast<const float4*>(&h1[((size_t)(b * S1 + s + kk)) * DH + ic]);
    *reinterpret_cast<float4*>(&out[(size_t)m * 1536 + c4]) = v;
}

// out[c][kk*IC+ic] = w[c][ic][kk]   (torch Conv1d [OC, IC, 3])
__global__ void repack_w_kernel(const float* __restrict__ w, float* __restrict__ out, int OC, int IC)
{
    int K = IC * 3;
    int idx = blockIdx.x * 256 + threadIdx.x;
    if (idx >= OC * K) return;
    int c = idx / K, r = idx % K;
    int kk = r / IC, ic = r % IC;
    out[idx] = w[(size_t)c * K + ic * 3 + kk];
}

// ---------------- positional encoding add (double range-reduction: fast-math safe) ----------------
__global__ void pos_add_kernel(float* __restrict__ h)
{
    int idx = blockIdx.x * 256 + threadIdx.x;
    if (idx >= BATCH * SEQ * D_MODEL) return;
    int d = idx & (D_MODEL - 1);
    int s = (idx >> 10) & (SEQ - 1);
    int i2 = d & ~1;
    float freq = expf((float)i2 * (-9.210340371976184f / 1024.0f));
    float ang  = (float)s * freq;                        // fp32, matches jnp rounding
    double angd = (double)ang;
    double kq = rint(angd * 0.15915494309189535);        // ang / (2*pi)
    float r = (float)(angd - kq * 6.283185307179586);    // |r| <= pi
    float pe = (d & 1) ? cosf(r) : sinf(r);
    h[idx] += pe;
}

// ---------------- LayerNorm (torch-style: unbiased var, eps added to std) ----------------
__global__ void __launch_bounds__(256) layernorm_kernel(
    const float* __restrict__ x, const float* __restrict__ w,
    const float* __restrict__ b, float* __restrict__ y)
{
    __shared__ float red[8];
    __shared__ float sh_mean, sh_inv;
    const int row = blockIdx.x;
    const int t = threadIdx.x;
    const float* xr = x + (size_t)row * D_MODEL;
    float4 v = *reinterpret_cast<const float4*>(&xr[t * 4]);

    float s = v.x + v.y + v.z + v.w;
#pragma unroll
    for (int o = 16; o > 0; o >>= 1) s += __shfl_xor_sync(0xffffffffu, s, o);
    if ((t & 31) == 0) red[t >> 5] = s;
    __syncthreads();
    if (t == 0) {
        float tot = 0.f;
#pragma unroll
        for (int i = 0; i < 8; i++) tot += red[i];
        sh_mean = tot * (1.0f / 1024.0f);
    }
    __syncthreads();
    float mean = sh_mean;
    float d0 = v.x - mean, d1 = v.y - mean, d2 = v.z - mean, d3 = v.w - mean;
    float sq = d0 * d0 + d1 * d1 + d2 * d2 + d3 * d3;
#pragma unroll
    for (int o = 16; o > 0; o >>= 1) sq += __shfl_xor_sync(0xffffffffu, sq, o);
    if ((t & 31) == 0) red[t >> 5] = sq;
    __syncthreads();
    if (t == 0) {
        float tot = 0.f;
#pragma unroll
        for (int i = 0; i < 8; i++) tot += red[i];
        float var = tot * (1.0f / 1023.0f);              // unbiased (N-1)
        sh_inv = 1.0f / (sqrtf(var) + EPSF);             // eps added to std
    }
    __syncthreads();
    float inv = sh_inv;
    float4 w4 = *reinterpret_cast<const float4*>(&w[t * 4]);
    float4 b4 = *reinterpret_cast<const float4*>(&b[t * 4]);
    float4 o4;
    o4.x = w4.x * d0 * inv + b4.x;
    o4.y = w4.y * d1 * inv + b4.y;
    o4.z = w4.z * d2 * inv + b4.z;
    o4.w = w4.w * d3 * inv + b4.w;
    *reinterpret_cast<float4*>(&y[(size_t)row * D_MODEL + t * 4]) = o4;
}

// ---------------- fused softsign attention (flash-style, no score materialization) ----------------
#define ATT_PAD 68
#define ATT_SMEM_BYTES (4 * 64 * ATT_PAD * 4)

__device__ __forceinline__ float softsign_scaled(float x)
{
    float t = x * 0.125f;                   // 1/sqrt(HDIM)
    return t / (1.0f + fabsf(t));
}

__global__ void __launch_bounds__(256) attention_kernel(
    const float* __restrict__ Q, const float* __restrict__ K,
    const float* __restrict__ V, float* __restrict__ O)
{
    extern __shared__ float sm[];
    float* Qs = sm;                         // [64][ATT_PAD]
    float* KT = sm + 64 * ATT_PAD;          // [k][j]  (transposed)
    float* Vs = sm + 2 * 64 * ATT_PAD;      // [j][d]
    float* Ss = sm + 3 * 64 * ATT_PAD;      // [i][j]

    const int i0 = blockIdx.x * 64;
    const int h  = blockIdx.y;
    const int b  = blockIdx.z;
    const int tid = threadIdx.x;
    const int ty = tid >> 4, tx = tid & 15;
    const int r0 = ty * 4, c0 = tx * 4;
    const int lrow = tid >> 4;
    const int lcol = (tid & 15) * 4;

    const size_t base = ((size_t)(b * SEQ)) * D_MODEL + h * HDIM;

#pragma unroll
    for (int it = 0; it < 4; it++) {
        int rr = lrow + it * 16;
        float4 q4 = *reinterpret_cast<const float4*>(&Q[base + (size_t)(i0 + rr) * D_MODEL + lcol]);
        *reinterpret_cast<float4*>(&Qs[rr * ATT_PAD + lcol]) = q4;
    }

    float acc[4][4];
#pragma unroll
    for (int i = 0; i < 4; i++)
#pragma unroll
        for (int j = 0; j < 4; j++) acc[i][j] = 0.f;

    for (int j0 = 0; j0 < SEQ; j0 += 64) {
        __syncthreads();
#pragma unroll
        for (int it = 0; it < 4; it++) {
            int rr = lrow + it * 16;
            float4 k4 = *reinterpret_cast<const float4*>(&K[base + (size_t)(j0 + rr) * D_MODEL + lcol]);
            KT[(lcol + 0) * ATT_PAD + rr] = k4.x;
            KT[(lcol + 1) * ATT_PAD + rr] = k4.y;
            KT[(lcol + 2) * ATT_PAD + rr] = k4.z;
            KT[(lcol + 3) * ATT_PAD + rr] = k4.w;
            float4 v4 = *reinterpret_cast<const float4*>(&V[base + (size_t)(j0 + rr) * D_MODEL + lcol]);
            *reinterpret_cast<float4*>(&Vs[rr * ATT_PAD + lcol]) = v4;
        }
        __syncthreads();

        float sreg[4][4];
#pragma unroll
        for (int i = 0; i < 4; i++)
#pragma unroll
            for (int j = 0; j < 4; j++) sreg[i][j] = 0.f;

#pragma unroll 16
        for (int kk = 0; kk < 64; kk++) {
            float4 kb = *reinterpret_cast<const float4*>(&KT[kk * ATT_PAD + c0]);
#pragma unroll
            for (int i = 0; i < 4; i++) {
                float qa = Qs[(r0 + i) * ATT_PAD + kk];
                sreg[i][0] = fmaf(qa, kb.x, sreg[i][0]);
                sreg[i][1] = fmaf(qa, kb.y, sreg[i][1]);
                sreg[i][2] = fmaf(qa, kb.z, sreg[i][2]);
                sreg[i][3] = fmaf(qa, kb.w, sreg[i][3]);
            }
        }
#pragma unroll
        for (int i = 0; i < 4; i++) {
            float4 t4;
            t4.x = softsign_scaled(sreg[i][0]);
            t4.y = softsign_scaled(sreg[i][1]);
            t4.z = softsign_scaled(sreg[i][2]);
            t4.w = softsign_scaled(sreg[i][3]);
            *reinterpret_cast<float4*>(&Ss[(r0 + i) * ATT_PAD + c0]) = t4;
        }
        __syncthreads();
#pragma unroll 16
        for (int jj = 0; jj < 64; jj++) {
            float4 vb = *reinterpret_cast<const float4*>(&Vs[jj * ATT_PAD + c0]);
#pragma unroll
            for (int i = 0; i < 4; i++) {
                float sa = Ss[(r0 + i) * ATT_PAD + jj];
                acc[i][0] = fmaf(sa, vb.x, acc[i][0]);
                acc[i][1] = fmaf(sa, vb.y, acc[i][1]);
                acc[i][2] = fmaf(sa, vb.z, acc[i][2]);
                acc[i][3] = fmaf(sa, vb.w, acc[i][3]);
            }
        }
    }

#pragma unroll
    for (int i = 0; i < 4; i++) {
        float4 o4 = make_float4(acc[i][0], acc[i][1], acc[i][2], acc[i][3]);
        *reinterpret_cast<float4*>(&O[base + (size_t)(i0 + r0 + i) * D_MODEL + c0]) = o4;
    }
}

// ---------------- mean pool over sequence + final fc ----------------
__global__ void pool_kernel(const float* __restrict__ h, float* __restrict__ out)
{
    int idx = blockIdx.x * 256 + threadIdx.x;
    if (idx >= BATCH * D_MODEL) return;
    int b = idx >> 10, d = idx & (D_MODEL - 1);
    const float* p = h + (size_t)(b * SEQ) * D_MODEL + d;
    float a[8];
#pragma unroll
    for (int i = 0; i < 8; i++) a[i] = 0.f;
    for (int i = 0; i < SEQ; i += 8) {
#pragma unroll
        for (int u = 0; u < 8; u++) a[u] += p[(size_t)(i + u) * D_MODEL];
    }
    float s = ((a[0] + a[1]) + (a[2] + a[3])) + ((a[4] + a[5]) + (a[6] + a[7]));
    out[idx] = s * (1.0f / 1024.0f);
}

__global__ void fc_kernel(const float* __restrict__ pool, const float* __restrict__ fcw,
                          const float* __restrict__ fcb, float* __restrict__ out)
{
    __shared__ float red[8];
    int b = blockIdx.x, t = threadIdx.x;
    float4 p  = *reinterpret_cast<const float4*>(&pool[b * D_MODEL + t * 4]);
    float4 w4 = *reinterpret_cast<const float4*>(&fcw[t * 4]);
    float s = p.x * w4.x + p.y * w4.y + p.z * w4.z + p.w * w4.w;
#pragma unroll
    for (int o = 16; o > 0; o >>= 1) s += __shfl_xor_sync(0xffffffffu, s, o);
    if ((t & 31) == 0) red[t >> 5] = s;
    __syncthreads();
    if (t == 0) {
        float tot = 0.f;
#pragma unroll
        for (int i = 0; i < 8; i++) tot += red[i];
        out[b] = tot + fcb[0];
    }
}

// ---------------- host orchestration ----------------
extern "C" void kernel_launch(void* const* d_in, const int* in_sizes, int n_in,
                              void* d_out, int out_size)
{
    (void)in_sizes; (void)n_in; (void)out_size;
    const float* x       = (const float*)d_in[0];
    const float* conv1_w = (const float*)d_in[1];
    const float* conv1_b = (const float*)d_in[2];
    const float* conv2_w = (const float*)d_in[3];
    const float* conv2_b = (const float*)d_in[4];
    const float* lnA_w   = (const float*)d_in[5];
    const float* lnA_b   = (const float*)d_in[6];
    const float* q_w     = (const float*)d_in[7];
    const float* q_b     = (const float*)d_in[8];
    const float* k_w     = (const float*)d_in[9];
    const float* k_b     = (const float*)d_in[10];
    const float* v_w     = (const float*)d_in[11];
    const float* v_b     = (const float*)d_in[12];
    const float* o_w     = (const float*)d_in[13];
    const float* o_b     = (const float*)d_in[14];
    const float* lnB_w   = (const float*)d_in[15];
    const float* lnB_b   = (const float*)d_in[16];
    const float* f1_w    = (const float*)d_in[17];
    const float* f1_b    = (const float*)d_in[18];
    const float* f2_w    = (const float*)d_in[19];
    const float* f2_b    = (const float*)d_in[20];
    const float* fc_w    = (const float*)d_in[21];
    const float* fc_b    = (const float*)d_in[22];
    float* out = (float*)d_out;

    float *p_h, *p_hn, *p_q, *p_k, *p_v, *p_wv, *p_ff, *p_h1, *p_im1, *p_im2, *p_w1r, *p_w2r, *p_pool;
    cudaGetSymbolAddress((void**)&p_h,   g_h);
    cudaGetSymbolAddress((void**)&p_hn,  g_hn);
    cudaGetSymbolAddress((void**)&p_q,   g_q);
    cudaGetSymbolAddress((void**)&p_k,   g_k);
    cudaGetSymbolAddress((void**)&p_v,   g_v);
    cudaGetSymbolAddress((void**)&p_wv,  g_wv);
    cudaGetSymbolAddress((void**)&p_ff,  g_ff);
    cudaGetSymbolAddress((void**)&p_h1,  g_h1);
    cudaGetSymbolAddress((void**)&p_im1, g_im1);
    cudaGetSymbolAddress((void**)&p_im2, g_im2);
    cudaGetSymbolAddress((void**)&p_w1r, g_w1r);
    cudaGetSymbolAddress((void**)&p_w2r, g_w2r);
    cudaGetSymbolAddress((void**)&p_pool, g_pool);

    cudaFuncSetAttribute(attention_kernel, cudaFuncAttributeMaxDynamicSharedMemorySize, ATT_SMEM_BYTES);

    // conv frontend: repack weights, im2col, GEMM
    repack_w_kernel<<<(DH * 192 + 255) / 256, 256>>>(conv1_w, p_w1r, DH, D_IN);
    repack_w_kernel<<<(D_MODEL * 1536 + 255) / 256, 256>>>(conv2_w, p_w2r, D_MODEL, DH);

    im2col1_kernel<<<(BATCH * S1 * (192 / 4) + 255) / 256, 256>>>(x, p_im1);
    sgemm_tn<false, false><<<dim3(DH / BN, (BATCH * S1 + BM - 1) / BM), 256>>>(
        p_im1, p_w1r, conv1_b, nullptr, p_h1, BATCH * S1, DH, 192);

    im2col2_kernel<<<(BATCH * SEQ * (1536 / 4) + 255) / 256, 256>>>(p_h1, p_im2);
    sgemm_tn<false, false><<<dim3(D_MODEL / BN, (BATCH * SEQ) / BM), 256>>>(
        p_im2, p_w2r, conv2_b, nullptr, p_h, BATCH * SEQ, D_MODEL, 1536);

    pos_add_kernel<<<(BATCH * SEQ * D_MODEL) / 256, 256>>>(p_h);

    const int M = BATCH * SEQ;                 // 4096
    const dim3 gD(D_MODEL / BN, M / BM);       // 8 x 32
    const dim3 gF(FFDIM / BN, M / BM);         // 16 x 32

    for (int l = 0; l < NLAYER; l++) {
        size_t wo  = (size_t)l * D_MODEL * D_MODEL;
        size_t bo  = (size_t)l * D_MODEL;
        size_t f1wo = (size_t)l * FFDIM * D_MODEL;
        size_t f1bo = (size_t)l * FFDIM;
        size_t f2wo = (size_t)l * D_MODEL * FFDIM;

        layernorm_kernel<<<M, 256>>>(p_h, lnA_w + bo, lnA_b + bo, p_hn);
        sgemm_tn<false, false><<<gD, 256>>>(p_hn, q_w + wo, q_b + bo, nullptr, p_q, M, D_MODEL, D_MODEL);
        sgemm_tn<false, false><<<gD, 256>>>(p_hn, k_w + wo, k_b + bo, nullptr, p_k, M, D_MODEL, D_MODEL);
        sgemm_tn<false, false><<<gD, 256>>>(p_hn, v_w + wo, v_b + bo, nullptr, p_v, M, D_MODEL, D_MODEL);

        attention_kernel<<<dim3(SEQ / 64, NHEAD, BATCH), 256, ATT_SMEM_BYTES>>>(p_q, p_k, p_v, p_wv);

        sgemm_tn<false, true><<<gD, 256>>>(p_wv, o_w + wo, o_b + bo, p_h, p_h, M, D_MODEL, D_MODEL);

        layernorm_kernel<<<M, 256>>>(p_h, lnB_w + bo, lnB_b + bo, p_hn);
        sgemm_tn<true, false><<<gF, 256>>>(p_hn, f1_w + f1wo, f1_b + f1bo, nullptr, p_ff, M, FFDIM, D_MODEL);
        sgemm_tn<false, true><<<gD, 256>>>(p_ff, f2_w + f2wo, f2_b + bo, p_h, p_h, M, D_MODEL, FFDIM);
    }

    pool_kernel<<<(BATCH * D_MODEL) / 256, 256>>>(p_h, p_pool);
    fc_kernel<<<BATCH, 256>>>(p_pool, fc_w, fc_b, out);
}

// round 3
// speedup vs baseline: 1.7354x; 1.7354x over previous
#include <cuda_runtime.h>
#include <cuda_bf16.h>
#include <math.h>
#include <stdint.h>

// ---------------- problem dims ----------------
#define BATCH   4
#define S_IN    1028
#define D_IN    64
#define S1      1026      // after conv1 (VALID, k=3)
#define SEQ     1024      // after conv2
#define DH      512       // D/2
#define D_MODEL 1024
#define NHEAD   16
#define HDIM    64
#define NLAYER  4
#define FFDIM   2048
#define EPSF    1e-6f

// ---------------- scratch (device globals; no allocation allowed) ----------------
__device__ float g_h  [BATCH*SEQ*D_MODEL];
__device__ float g_hn [BATCH*SEQ*D_MODEL];
__device__ float g_q  [BATCH*SEQ*D_MODEL];
__device__ float g_k  [BATCH*SEQ*D_MODEL];
__device__ float g_v  [BATCH*SEQ*D_MODEL];
__device__ float g_wv [BATCH*SEQ*D_MODEL];
__device__ float g_ff [BATCH*SEQ*FFDIM];
__device__ float g_h1 [BATCH*S1*DH];
__device__ float g_im1[(size_t)BATCH*S1*192];
__device__ float g_im2[(size_t)BATCH*SEQ*1536];
__device__ float g_w1r[DH*192];
__device__ float g_w2r[D_MODEL*1536];
__device__ float g_pool[BATCH*D_MODEL];

// ================= helpers =================
__device__ __forceinline__ uint32_t smem_u32(const void* p) {
    uint32_t a;
    asm("{ .reg .u64 t; cvta.to.shared.u64 t, %1; cvt.u32.u64 %0, t; }" : "=r"(a) : "l"(p));
    return a;
}
// pack 2 fp32 -> bf16x2 (first arg -> low 16 bits)
__device__ __forceinline__ uint32_t bf16x2_of(float lo, float hi) {
    uint32_t r;
    asm("cvt.rn.bf16x2.f32 %0, %1, %2;" : "=r"(r) : "f"(hi), "f"(lo));
    return r;
}
__device__ __forceinline__ void sts_v2(uint32_t addr, uint32_t a, uint32_t b) {
    asm volatile("st.shared.v2.b32 [%0], {%1, %2};" :: "r"(addr), "r"(a), "r"(b) : "memory");
}
#define LDSM_X4(r, addr) \
    asm volatile("ldmatrix.sync.aligned.m8n8.x4.shared.b16 {%0,%1,%2,%3}, [%4];" \
        : "=r"((r)[0]), "=r"((r)[1]), "=r"((r)[2]), "=r"((r)[3]) : "r"(addr))
#define LDSM_X2(r, addr) \
    asm volatile("ldmatrix.sync.aligned.m8n8.x2.shared.b16 {%0,%1}, [%2];" \
        : "=r"((r)[0]), "=r"((r)[1]) : "r"(addr))
#define MMA16816(d, a, b) \
    asm volatile("mma.sync.aligned.m16n8k16.row.col.f32.bf16.bf16.f32 " \
        "{%0,%1,%2,%3}, {%4,%5,%6,%7}, {%8,%9}, {%0,%1,%2,%3};" \
        : "+f"((d)[0]), "+f"((d)[1]), "+f"((d)[2]), "+f"((d)[3]) \
        : "r"((a)[0]), "r"((a)[1]), "r"((a)[2]), "r"((a)[3]), "r"((b)[0]), "r"((b)[1]))

// ================= split-bf16 tensor-core GEMM: C[M,N] = A[M,K] @ B[N,K]^T =================
// fp32 emulation: x = hi + lo (bf16); C += Ahi*Bhi + Ahi*Blo + Alo*Bhi (fp32 accumulate).
// CTA tile 128x128, BK=32, 8 warps of 64x32. SMEM rows padded: 32+8 bf16 = 80 bytes/row.
#define ROWB   80u
#define PLANE  10240u            // 128 rows * 80 B
#define STG    (4u * PLANE)      // Ahi, Alo, Bhi, Blo
#define GEMM_SMEM (2u * STG)     // double buffered = 81920 B

template<bool RELU, bool RESID>
__global__ void __launch_bounds__(256) gemm_mma(
    const float* __restrict__ A, const float* __restrict__ B,
    const float* __restrict__ bias, const float* __restrict__ resid,
    float* __restrict__ C, int M, int N, int K)
{
    extern __shared__ char smem[];
    const uint32_t sb = smem_u32(smem);
    const int tid  = threadIdx.x;
    const int wid  = tid >> 5;
    const int lane = tid & 31;
    const int crow = blockIdx.y * 128;
    const int ccol = blockIdx.x * 128;
    const int NK   = K >> 5;

    // ---- loader mapping: 2 threads per row, 16 floats each ----
    const int lrow = tid >> 1;            // 0..127
    const int lk   = (tid & 1) * 16;      // 0 or 16
    int ga = crow + lrow; if (ga > M - 1) ga = M - 1;
    const float* arow = A + (size_t)ga * K + lk;
    const float* brow = B + (size_t)(ccol + lrow) * K + lk;
    const uint32_t ldst = sb + (uint32_t)lrow * ROWB + (uint32_t)lk * 2;

    float4 ra[4], rb[4];

    // ---- warp tile ----
    const int wm = wid & 1;               // 0..1 -> 64-row half
    const int wn = wid >> 1;              // 0..3 -> 32-col quarter
    const uint32_t a_off = (uint32_t)(wm * 64 + (lane & 15)) * ROWB + (uint32_t)((lane >> 4) << 4);
    const uint32_t b_off = (uint32_t)(wn * 32 + (lane & 7)) * ROWB + (uint32_t)(((lane >> 3) & 1) << 4);

    float acc[4][4][4];
#pragma unroll
    for (int i = 0; i < 4; i++)
#pragma unroll
        for (int j = 0; j < 4; j++)
#pragma unroll
            for (int e = 0; e < 4; e++) acc[i][j][e] = 0.f;

    // ---- prologue: load chunk 0 and store to stage 0 ----
#pragma unroll
    for (int i = 0; i < 4; i++) {
        ra[i] = *reinterpret_cast<const float4*>(arow + i * 4);
        rb[i] = *reinterpret_cast<const float4*>(brow + i * 4);
    }
#pragma unroll
    for (int i = 0; i < 4; i++) {
        float4 v = ra[i];
        uint32_t h0 = bf16x2_of(v.x, v.y), h1 = bf16x2_of(v.z, v.w);
        uint32_t l0 = bf16x2_of(v.x - __uint_as_float(h0 << 16),
                                v.y - __uint_as_float(h0 & 0xffff0000u));
        uint32_t l1 = bf16x2_of(v.z - __uint_as_float(h1 << 16),
                                v.w - __uint_as_float(h1 & 0xffff0000u));
        sts_v2(ldst + i * 8, h0, h1);
        sts_v2(ldst + PLANE + i * 8, l0, l1);
        v = rb[i];
        h0 = bf16x2_of(v.x, v.y); h1 = bf16x2_of(v.z, v.w);
        l0 = bf16x2_of(v.x - __uint_as_float(h0 << 16),
                       v.y - __uint_as_float(h0 & 0xffff0000u));
        l1 = bf16x2_of(v.z - __uint_as_float(h1 << 16),
                       v.w - __uint_as_float(h1 & 0xffff0000u));
        sts_v2(ldst + 2 * PLANE + i * 8, h0, h1);
        sts_v2(ldst + 3 * PLANE + i * 8, l0, l1);
    }
    __syncthreads();

    for (int kb = 0; kb < NK; kb++) {
        const uint32_t s = (uint32_t)(kb & 1) * STG;

        // prefetch next chunk into registers
        if (kb + 1 < NK) {
            const float* an = arow + (size_t)(kb + 1) * 32;
            const float* bn = brow + (size_t)(kb + 1) * 32;
#pragma unroll
            for (int i = 0; i < 4; i++) {
                ra[i] = *reinterpret_cast<const float4*>(an + i * 4);
                rb[i] = *reinterpret_cast<const float4*>(bn + i * 4);
            }
        }

        // compute on stage s
#pragma unroll
        for (int ks = 0; ks < 2; ks++) {
            const uint32_t koff = (uint32_t)ks * 32;
            uint32_t ah[4][4], al[4][4];
#pragma unroll
            for (int i = 0; i < 4; i++) {
                LDSM_X4(ah[i], sb + s + a_off + (uint32_t)i * (16 * ROWB) + koff);
                LDSM_X4(al[i], sb + s + PLANE + a_off + (uint32_t)i * (16 * ROWB) + koff);
            }
#pragma unroll
            for (int j = 0; j < 4; j++) {
                uint32_t bh[2], bl[2];
                LDSM_X2(bh, sb + s + 2 * PLANE + b_off + (uint32_t)j * (8 * ROWB) + koff);
                LDSM_X2(bl, sb + s + 3 * PLANE + b_off + (uint32_t)j * (8 * ROWB) + koff);
#pragma unroll
                for (int i = 0; i < 4; i++) {
                    MMA16816(acc[i][j], ah[i], bh);
                    MMA16816(acc[i][j], ah[i], bl);
                    MMA16816(acc[i][j], al[i], bh);
                }
            }
        }

        // store next chunk into the other stage
        if (kb + 1 < NK) {
            const uint32_t d = ldst + (uint32_t)((kb + 1) & 1) * STG;
#pragma unroll
            for (int i = 0; i < 4; i++) {
                float4 v = ra[i];
                uint32_t h0 = bf16x2_of(v.x, v.y), h1 = bf16x2_of(v.z, v.w);
                uint32_t l0 = bf16x2_of(v.x - __uint_as_float(h0 << 16),
                                        v.y - __uint_as_float(h0 & 0xffff0000u));
                uint32_t l1 = bf16x2_of(v.z - __uint_as_float(h1 << 16),
                                        v.w - __uint_as_float(h1 & 0xffff0000u));
                sts_v2(d + i * 8, h0, h1);
                sts_v2(d + PLANE + i * 8, l0, l1);
                v = rb[i];
                h0 = bf16x2_of(v.x, v.y); h1 = bf16x2_of(v.z, v.w);
                l0 = bf16x2_of(v.x - __uint_as_float(h0 << 16),
                               v.y - __uint_as_float(h0 & 0xffff0000u));
                l1 = bf16x2_of(v.z - __uint_as_float(h1 << 16),
                               v.w - __uint_as_float(h1 & 0xffff0000u));
                sts_v2(d + 2 * PLANE + i * 8, h0, h1);
                sts_v2(d + 3 * PLANE + i * 8, l0, l1);
            }
        }
        __syncthreads();
    }

    // ---- epilogue: direct register -> gmem stores (float2) ----
#pragma unroll
    for (int i = 0; i < 4; i++) {
        const int rbase = crow + wm * 64 + i * 16 + (lane >> 2);
#pragma unroll
        for (int h = 0; h < 2; h++) {
            const int r = rbase + h * 8;
            if (r >= M) continue;
            const size_t ro = (size_t)r * N;
#pragma unroll
            for (int j = 0; j < 4; j++) {
                const int c = ccol + wn * 32 + j * 8 + (lane & 3) * 2;
                float2 v = make_float2(acc[i][j][2 * h], acc[i][j][2 * h + 1]);
                v.x += bias[c]; v.y += bias[c + 1];
                if (RELU) { v.x = fmaxf(v.x, 0.f); v.y = fmaxf(v.y, 0.f); }
                if (RESID) {
                    float2 r2 = *reinterpret_cast<const float2*>(&resid[ro + c]);
                    v.x += r2.x; v.y += r2.y;
                }
                *reinterpret_cast<float2*>(&C[ro + c]) = v;
            }
        }
    }
}

// ---------------- im2col + weight repack for the conv frontend ----------------
__global__ void im2col1_kernel(const float* __restrict__ x, float* __restrict__ out)
{
    const int COLS4 = 192 / 4;
    int idx = blockIdx.x * 256 + threadIdx.x;
    if (idx >= BATCH * S1 * COLS4) return;
    int m  = idx / COLS4;
    int c4 = (idx % COLS4) * 4;
    int b  = m / S1, s = m % S1;
    int kk = c4 / D_IN, ic = c4 % D_IN;
    float4 v = *reinterpret_cast<const float4*>(&x[((size_t)(b * S_IN + s + kk)) * D_IN + ic]);
    *reinterpret_cast<float4*>(&out[(size_t)m * 192 + c4]) = v;
}

__global__ void im2col2_kernel(const float* __restrict__ h1, float* __restrict__ out)
{
    const int COLS4 = 1536 / 4;
    int idx = blockIdx.x * 256 + threadIdx.x;
    if (idx >= BATCH * SEQ * COLS4) return;
    int m  = idx / COLS4;
    int c4 = (idx % COLS4) * 4;
    int b  = m / SEQ, s = m % SEQ;
    int kk = c4 / DH, ic = c4 % DH;
    float4 v = *reinterpret_cast<const float4*>(&h1[((size_t)(b * S1 + s + kk)) * DH + ic]);
    *reinterpret_cast<float4*>(&out[(size_t)m * 1536 + c4]) = v;
}

__global__ void repack_w_kernel(const float* __restrict__ w, float* __restrict__ out, int OC, int IC)
{
    int K = IC * 3;
    int idx = blockIdx.x * 256 + threadIdx.x;
    if (idx >= OC * K) return;
    int c = idx / K, r = idx % K;
    int kk = r / IC, ic = r % IC;
    out[idx] = w[(size_t)c * K + ic * 3 + kk];
}

// ---------------- positional encoding add ----------------
__global__ void pos_add_kernel(float* __restrict__ h)
{
    int idx = blockIdx.x * 256 + threadIdx.x;
    if (idx >= BATCH * SEQ * D_MODEL) return;
    int d = idx & (D_MODEL - 1);
    int s = (idx >> 10) & (SEQ - 1);
    int i2 = d & ~1;
    float freq = expf((float)i2 * (-9.210340371976184f / 1024.0f));
    float ang  = (float)s * freq;
    double angd = (double)ang;
    double kq = rint(angd * 0.15915494309189535);
    float r = (float)(angd - kq * 6.283185307179586);
    float pe = (d & 1) ? cosf(r) : sinf(r);
    h[idx] += pe;
}

// ---------------- LayerNorm (torch-style) ----------------
__global__ void __launch_bounds__(256) layernorm_kernel(
    const float* __restrict__ x, const float* __restrict__ w,
    const float* __restrict__ b, float* __restrict__ y)
{
    __shared__ float red[8];
    __shared__ float sh_mean, sh_inv;
    const int row = blockIdx.x;
    const int t = threadIdx.x;
    const float* xr = x + (size_t)row * D_MODEL;
    float4 v = *reinterpret_cast<const float4*>(&xr[t * 4]);

    float s = v.x + v.y + v.z + v.w;
#pragma unroll
    for (int o = 16; o > 0; o >>= 1) s += __shfl_xor_sync(0xffffffffu, s, o);
    if ((t & 31) == 0) red[t >> 5] = s;
    __syncthreads();
    if (t == 0) {
        float tot = 0.f;
#pragma unroll
        for (int i = 0; i < 8; i++) tot += red[i];
        sh_mean = tot * (1.0f / 1024.0f);
    }
    __syncthreads();
    float mean = sh_mean;
    float d0 = v.x - mean, d1 = v.y - mean, d2 = v.z - mean, d3 = v.w - mean;
    float sq = d0 * d0 + d1 * d1 + d2 * d2 + d3 * d3;
#pragma unroll
    for (int o = 16; o > 0; o >>= 1) sq += __shfl_xor_sync(0xffffffffu, sq, o);
    if ((t & 31) == 0) red[t >> 5] = sq;
    __syncthreads();
    if (t == 0) {
        float tot = 0.f;
#pragma unroll
        for (int i = 0; i < 8; i++) tot += red[i];
        float var = tot * (1.0f / 1023.0f);
        sh_inv = 1.0f / (sqrtf(var) + EPSF);
    }
    __syncthreads();
    float inv = sh_inv;
    float4 w4 = *reinterpret_cast<const float4*>(&w[t * 4]);
    float4 b4 = *reinterpret_cast<const float4*>(&b[t * 4]);
    float4 o4;
    o4.x = w4.x * d0 * inv + b4.x;
    o4.y = w4.y * d1 * inv + b4.y;
    o4.z = w4.z * d2 * inv + b4.z;
    o4.w = w4.w * d3 * inv + b4.w;
    *reinterpret_cast<float4*>(&y[(size_t)row * D_MODEL + t * 4]) = o4;
}

// ---------------- fused softsign attention (flash-style, fp32) ----------------
#define ATT_PAD 68
#define ATT_SMEM_BYTES (4 * 64 * ATT_PAD * 4)

__device__ __forceinline__ float softsign_scaled(float x)
{
    float t = x * 0.125f;
    return t / (1.0f + fabsf(t));
}

__global__ void __launch_bounds__(256) attention_kernel(
    const float* __restrict__ Q, const float* __restrict__ K,
    const float* __restrict__ V, float* __restrict__ O)
{
    extern __shared__ float sm[];
    float* Qs = sm;
    float* KT = sm + 64 * ATT_PAD;
    float* Vs = sm + 2 * 64 * ATT_PAD;
    float* Ss = sm + 3 * 64 * ATT_PAD;

    const int i0 = blockIdx.x * 64;
    const int h  = blockIdx.y;
    const int b  = blockIdx.z;
    const int tid = threadIdx.x;
    const int ty = tid >> 4, tx = tid & 15;
    const int r0 = ty * 4, c0 = tx * 4;
    const int lrow = tid >> 4;
    const int lcol = (tid & 15) * 4;

    const size_t base = ((size_t)(b * SEQ)) * D_MODEL + h * HDIM;

#pragma unroll
    for (int it = 0; it < 4; it++) {
        int rr = lrow + it * 16;
        float4 q4 = *reinterpret_cast<const float4*>(&Q[base + (size_t)(i0 + rr) * D_MODEL + lcol]);
        *reinterpret_cast<float4*>(&Qs[rr * ATT_PAD + lcol]) = q4;
    }

    float acc[4][4];
#pragma unroll
    for (int i = 0; i < 4; i++)
#pragma unroll
        for (int j = 0; j < 4; j++) acc[i][j] = 0.f;

    for (int j0 = 0; j0 < SEQ; j0 += 64) {
        __syncthreads();
#pragma unroll
        for (int it = 0; it < 4; it++) {
            int rr = lrow + it * 16;
            float4 k4 = *reinterpret_cast<const float4*>(&K[base + (size_t)(j0 + rr) * D_MODEL + lcol]);
            KT[(lcol + 0) * ATT_PAD + rr] = k4.x;
            KT[(lcol + 1) * ATT_PAD + rr] = k4.y;
            KT[(lcol + 2) * ATT_PAD + rr] = k4.z;
            KT[(lcol + 3) * ATT_PAD + rr] = k4.w;
            float4 v4 = *reinterpret_cast<const float4*>(&V[base + (size_t)(j0 + rr) * D_MODEL + lcol]);
            *reinterpret_cast<float4*>(&Vs[rr * ATT_PAD + lcol]) = v4;
        }
        __syncthreads();

        float sreg[4][4];
#pragma unroll
        for (int i = 0; i < 4; i++)
#pragma unroll
            for (int j = 0; j < 4; j++) sreg[i][j] = 0.f;

#pragma unroll 16
        for (int kk = 0; kk < 64; kk++) {
            float4 kb = *reinterpret_cast<const float4*>(&KT[kk * ATT_PAD + c0]);
#pragma unroll
            for (int i = 0; i < 4; i++) {
                float qa = Qs[(r0 + i) * ATT_PAD + kk];
                sreg[i][0] = fmaf(qa, kb.x, sreg[i][0]);
                sreg[i][1] = fmaf(qa, kb.y, sreg[i][1]);
                sreg[i][2] = fmaf(qa, kb.z, sreg[i][2]);
                sreg[i][3] = fmaf(qa, kb.w, sreg[i][3]);
            }
        }
#pragma unroll
        for (int i = 0; i < 4; i++) {
            float4 t4;
            t4.x = softsign_scaled(sreg[i][0]);
            t4.y = softsign_scaled(sreg[i][1]);
            t4.z = softsign_scaled(sreg[i][2]);
            t4.w = softsign_scaled(sreg[i][3]);
            *reinterpret_cast<float4*>(&Ss[(r0 + i) * ATT_PAD + c0]) = t4;
        }
        __syncthreads();
#pragma unroll 16
        for (int jj = 0; jj < 64; jj++) {
            float4 vb = *reinterpret_cast<const float4*>(&Vs[jj * ATT_PAD + c0]);
#pragma unroll
            for (int i = 0; i < 4; i++) {
                float sa = Ss[(r0 + i) * ATT_PAD + jj];
                acc[i][0] = fmaf(sa, vb.x, acc[i][0]);
                acc[i][1] = fmaf(sa, vb.y, acc[i][1]);
                acc[i][2] = fmaf(sa, vb.z, acc[i][2]);
                acc[i][3] = fmaf(sa, vb.w, acc[i][3]);
            }
        }
    }

#pragma unroll
    for (int i = 0; i < 4; i++) {
        float4 o4 = make_float4(acc[i][0], acc[i][1], acc[i][2], acc[i][3]);
        *reinterpret_cast<float4*>(&O[base + (size_t)(i0 + r0 + i) * D_MODEL + c0]) = o4;
    }
}

// ---------------- mean pool + final fc ----------------
__global__ void pool_kernel(const float* __restrict__ h, float* __restrict__ out)
{
    int idx = blockIdx.x * 256 + threadIdx.x;
    if (idx >= BATCH * D_MODEL) return;
    int b = idx >> 10, d = idx & (D_MODEL - 1);
    const float* p = h + (size_t)(b * SEQ) * D_MODEL + d;
    float a[8];
#pragma unroll
    for (int i = 0; i < 8; i++) a[i] = 0.f;
    for (int i = 0; i < SEQ; i += 8) {
#pragma unroll
        for (int u = 0; u < 8; u++) a[u] += p[(size_t)(i + u) * D_MODEL];
    }
    float s = ((a[0] + a[1]) + (a[2] + a[3])) + ((a[4] + a[5]) + (a[6] + a[7]));
    out[idx] = s * (1.0f / 1024.0f);
}

__global__ void fc_kernel(const float* __restrict__ pool, const float* __restrict__ fcw,
                          const float* __restrict__ fcb, float* __restrict__ out)
{
    __shared__ float red[8];
    int b = blockIdx.x, t = threadIdx.x;
    float4 p  = *reinterpret_cast<const float4*>(&pool[b * D_MODEL + t * 4]);
    float4 w4 = *reinterpret_cast<const float4*>(&fcw[t * 4]);
    float s = p.x * w4.x + p.y * w4.y + p.z * w4.z + p.w * w4.w;
#pragma unroll
    for (int o = 16; o > 0; o >>= 1) s += __shfl_xor_sync(0xffffffffu, s, o);
    if ((t & 31) == 0) red[t >> 5] = s;
    __syncthreads();
    if (t == 0) {
        float tot = 0.f;
#pragma unroll
        for (int i = 0; i < 8; i++) tot += red[i];
        out[b] = tot + fcb[0];
    }
}

// ---------------- host orchestration ----------------
static inline void launch_gemm(int relu, int resid,
                               const float* A, const float* B, const float* bias,
                               const float* res, float* C, int M, int N, int K)
{
    dim3 grid(N / 128, (M + 127) / 128);
    if (relu)
        gemm_mma<true, false><<<grid, 256, GEMM_SMEM>>>(A, B, bias, res, C, M, N, K);
    else if (resid)
        gemm_mma<false, true><<<grid, 256, GEMM_SMEM>>>(A, B, bias, res, C, M, N, K);
    else
        gemm_mma<false, false><<<grid, 256, GEMM_SMEM>>>(A, B, bias, res, C, M, N, K);
}

extern "C" void kernel_launch(void* const* d_in, const int* in_sizes, int n_in,
                              void* d_out, int out_size)
{
    (void)in_sizes; (void)n_in; (void)out_size;
    const float* x       = (const float*)d_in[0];
    const float* conv1_w = (const float*)d_in[1];
    const float* conv1_b = (const float*)d_in[2];
    const float* conv2_w = (const float*)d_in[3];
    const float* conv2_b = (const float*)d_in[4];
    const float* lnA_w   = (const float*)d_in[5];
    const float* lnA_b   = (const float*)d_in[6];
    const float* q_w     = (const float*)d_in[7];
    const float* q_b     = (const float*)d_in[8];
    const float* k_w     = (const float*)d_in[9];
    const float* k_b     = (const float*)d_in[10];
    const float* v_w     = (const float*)d_in[11];
    const float* v_b     = (const float*)d_in[12];
    const float* o_w     = (const float*)d_in[13];
    const float* o_b     = (const float*)d_in[14];
    const float* lnB_w   = (const float*)d_in[15];
    const float* lnB_b   = (const float*)d_in[16];
    const float* f1_w    = (const float*)d_in[17];
    const float* f1_b    = (const float*)d_in[18];
    const float* f2_w    = (const float*)d_in[19];
    const float* f2_b    = (const float*)d_in[20];
    const float* fc_w    = (const float*)d_in[21];
    const float* fc_b    = (const float*)d_in[22];
    float* out = (float*)d_out;

    float *p_h, *p_hn, *p_q, *p_k, *p_v, *p_wv, *p_ff, *p_h1, *p_im1, *p_im2, *p_w1r, *p_w2r, *p_pool;
    cudaGetSymbolAddress((void**)&p_h,   g_h);
    cudaGetSymbolAddress((void**)&p_hn,  g_hn);
    cudaGetSymbolAddress((void**)&p_q,   g_q);
    cudaGetSymbolAddress((void**)&p_k,   g_k);
    cudaGetSymbolAddress((void**)&p_v,   g_v);
    cudaGetSymbolAddress((void**)&p_wv,  g_wv);
    cudaGetSymbolAddress((void**)&p_ff,  g_ff);
    cudaGetSymbolAddress((void**)&p_h1,  g_h1);
    cudaGetSymbolAddress((void**)&p_im1, g_im1);
    cudaGetSymbolAddress((void**)&p_im2, g_im2);
    cudaGetSymbolAddress((void**)&p_w1r, g_w1r);
    cudaGetSymbolAddress((void**)&p_w2r, g_w2r);
    cudaGetSymbolAddress((void**)&p_pool, g_pool);

    cudaFuncSetAttribute(attention_kernel, cudaFuncAttributeMaxDynamicSharedMemorySize, ATT_SMEM_BYTES);
    cudaFuncSetAttribute(gemm_mma<false, false>, cudaFuncAttributeMaxDynamicSharedMemorySize, GEMM_SMEM);
    cudaFuncSetAttribute(gemm_mma<true, false>,  cudaFuncAttributeMaxDynamicSharedMemorySize, GEMM_SMEM);
    cudaFuncSetAttribute(gemm_mma<false, true>,  cudaFuncAttributeMaxDynamicSharedMemorySize, GEMM_SMEM);

    // conv frontend
    repack_w_kernel<<<(DH * 192 + 255) / 256, 256>>>(conv1_w, p_w1r, DH, D_IN);
    repack_w_kernel<<<(D_MODEL * 1536 + 255) / 256, 256>>>(conv2_w, p_w2r, D_MODEL, DH);

    im2col1_kernel<<<(BATCH * S1 * (192 / 4) + 255) / 256, 256>>>(x, p_im1);
    launch_gemm(0, 0, p_im1, p_w1r, conv1_b, nullptr, p_h1, BATCH * S1, DH, 192);

    im2col2_kernel<<<(BATCH * SEQ * (1536 / 4) + 255) / 256, 256>>>(p_h1, p_im2);
    launch_gemm(0, 0, p_im2, p_w2r, conv2_b, nullptr, p_h, BATCH * SEQ, D_MODEL, 1536);

    pos_add_kernel<<<(BATCH * SEQ * D_MODEL) / 256, 256>>>(p_h);

    const int M = BATCH * SEQ;  // 4096

    for (int l = 0; l < NLAYER; l++) {
        size_t wo   = (size_t)l * D_MODEL * D_MODEL;
        size_t bo   = (size_t)l * D_MODEL;
        size_t f1wo = (size_t)l * FFDIM * D_MODEL;
        size_t f1bo = (size_t)l * FFDIM;
        size_t f2wo = (size_t)l * D_MODEL * FFDIM;

        layernorm_kernel<<<M, 256>>>(p_h, lnA_w + bo, lnA_b + bo, p_hn);
        launch_gemm(0, 0, p_hn, q_w + wo, q_b + bo, nullptr, p_q, M, D_MODEL, D_MODEL);
        launch_gemm(0, 0, p_hn, k_w + wo, k_b + bo, nullptr, p_k, M, D_MODEL, D_MODEL);
        launch_gemm(0, 0, p_hn, v_w + wo, v_b + bo, nullptr, p_v, M, D_MODEL, D_MODEL);

        attention_kernel<<<dim3(SEQ / 64, NHEAD, BATCH), 256, ATT_SMEM_BYTES>>>(p_q, p_k, p_v, p_wv);

        launch_gemm(0, 1, p_wv, o_w + wo, o_b + bo, p_h, p_h, M, D_MODEL, D_MODEL);

        layernorm_kernel<<<M, 256>>>(p_h, lnB_w + bo, lnB_b + bo, p_hn);
        launch_gemm(1, 0, p_hn, f1_w + f1wo, f1_b + f1bo, nullptr, p_ff, M, FFDIM, D_MODEL);
        launch_gemm(0, 1, p_ff, f2_w + f2wo, f2_b + bo, p_h, p_h, M, D_MODEL, FFDIM);
    }

    pool_kernel<<<(BATCH * D_MODEL) / 256, 256>>>(p_h, p_pool);
    fc_kernel<<<BATCH, 256>>>(p_pool, fc_w, fc_b, out);
}